// round 6
// baseline (speedup 1.0000x reference)
#include <cuda_runtime.h>

#define HH 128
#define WW 128
#define CC 64
#define NPIX (HH*WW)
#define GSTR 129

// scratch (allocation-free: __device__ globals)
__device__ float g_q[HH*CC*WW];   // [h][c][w]
__device__ float g_k[HH*CC*WW];   // [h][c][w]
__device__ float g_S[HH*WW*WW];   // [r][w][k]  (after prefix: PS over r)
__device__ float g_tmp[CC*HH*WW]; // [c][h][k]  hsum of v; after prefix: prefix over h

// ---------------------------------------------------------------------------
// Fused QKV: grid (32, 3); blockIdx.y selects q/k/v. For v, the horizontal
// 7-tap window sum is done in-block (each block holds 4 full image rows) and
// written straight to g_tmp — no separate hbox kernel, no g_v array.
// Dynamic smem: Ws[4096] | bs[64] | vbuf[64*128]
// ---------------------------------------------------------------------------
__global__ __launch_bounds__(512) void qkv_kernel(const float* __restrict__ x,
                                                  const float* __restrict__ Wq,
                                                  const float* __restrict__ bq,
                                                  const float* __restrict__ Wk,
                                                  const float* __restrict__ bk,
                                                  const float* __restrict__ Wv,
                                                  const float* __restrict__ bv)
{
    extern __shared__ float dsm[];
    float* Ws   = dsm;          // 4096
    float* bs   = dsm + 4096;   // 64
    float* vbuf = dsm + 4160;   // 64*128 (dest==2 only)

    int dest = blockIdx.y;
    const float* Wm   = (dest == 0) ? Wq : (dest == 1) ? Wk : Wv;
    const float* bias = (dest == 0) ? bq : (dest == 1) ? bk : bv;
    int tid = threadIdx.x;
    for (int i = tid; i < 4096; i += 512) Ws[i] = Wm[i];
    if (tid < 64) bs[tid] = bias[tid];
    __syncthreads();

    int slot = tid & 127;            // w coordinate (full row per 128 threads)
    int quarter = tid >> 7;          // 16-channel group
    int nbase = blockIdx.x * 512 + slot;

    float acc[16][4];
    #pragma unroll
    for (int i = 0; i < 16; i++)
        #pragma unroll
        for (int p = 0; p < 4; p++) acc[i][p] = 0.f;

    #pragma unroll 2
    for (int c = 0; c < 64; c++) {
        float xv[4];
        #pragma unroll
        for (int p = 0; p < 4; p++) xv[p] = x[c * NPIX + nbase + 128 * p];
        #pragma unroll
        for (int i = 0; i < 16; i++) {
            float wv = Ws[(quarter*16 + i)*64 + c];
            #pragma unroll
            for (int p = 0; p < 4; p++) acc[i][p] += wv * xv[p];
        }
    }

    if (dest < 2) {
        float* out = (dest == 0) ? g_q : g_k;
        #pragma unroll
        for (int i = 0; i < 16; i++) {
            int ch = quarter*16 + i;
            float b = bs[ch];
            #pragma unroll
            for (int p = 0; p < 4; p++) {
                int n = nbase + 128 * p;
                int h = n >> 7, w = n & 127;
                out[h*(CC*WW) + ch*WW + w] = acc[i][p] + b;
            }
        }
    } else {
        // v path: stage each row in vbuf, 7-tap hsum, write g_tmp[c][h][w]
        for (int p = 0; p < 4; p++) {
            __syncthreads();
            #pragma unroll
            for (int i = 0; i < 16; i++) {
                int ch = quarter*16 + i;
                vbuf[ch*128 + slot] = acc[i][p] + bs[ch];
            }
            __syncthreads();
            int h = blockIdx.x*4 + p;
            int klo = (slot - 3 < 0) ? 0 : slot - 3;
            int khi = (slot + 3 > 127) ? 127 : slot + 3;
            #pragma unroll
            for (int i = 0; i < 16; i++) {
                int ch = quarter*16 + i;
                const float* vr = vbuf + ch*128;
                float s = 0.f;
                for (int kk = klo; kk <= khi; kk++) s += vr[kk];
                g_tmp[ch*NPIX + h*128 + slot] = s;
            }
        }
    }
}

// ---------------------------------------------------------------------------
// Per-row Gram G_r = Q_r^T K_r (64-deep), then diagonal 7-sum -> S_r.
// ---------------------------------------------------------------------------
__global__ __launch_bounds__(512) void rowgram_kernel()
{
    extern __shared__ float sm[];
    float* Qs = sm;            // 64 x 128
    float* Ks = sm + 8192;     // 64 x 128
    float* G  = sm + 16384;    // 128 x GSTR

    int r = blockIdx.x;
    int tid = threadIdx.x;
    const float4* qrow = (const float4*)(g_q + r * 8192);
    const float4* krow = (const float4*)(g_k + r * 8192);
    float4* Qs4 = (float4*)Qs;
    float4* Ks4 = (float4*)Ks;
    for (int i = tid; i < 2048; i += 512) { Qs4[i] = qrow[i]; Ks4[i] = krow[i]; }
    __syncthreads();

    int lane = tid & 31, warp = tid >> 5;    // 16 warps
    int b0 = warp * 8;
    float acc[4][8];
    #pragma unroll
    for (int m = 0; m < 4; m++)
        #pragma unroll
        for (int j = 0; j < 8; j++) acc[m][j] = 0.f;

    #pragma unroll 4
    for (int c = 0; c < 64; c++) {
        float qv[4];
        #pragma unroll
        for (int m = 0; m < 4; m++) qv[m] = Qs[c*128 + lane + 32*m];
        #pragma unroll
        for (int j = 0; j < 8; j++) {
            float kv = Ks[c*128 + b0 + j];
            #pragma unroll
            for (int m = 0; m < 4; m++) acc[m][j] += qv[m] * kv;
        }
    }
    #pragma unroll
    for (int m = 0; m < 4; m++)
        #pragma unroll
        for (int j = 0; j < 8; j++)
            G[(lane + 32*m)*GSTR + b0 + j] = acc[m][j];
    __syncthreads();

    // S_r[w,k] = sum_{j=0..6} G[w-3+j, k-3+j] (OOB terms are zero)
    float* Sout = g_S + r * 16384;
    for (int idx = tid; idx < 16384; idx += 512) {
        int w = idx >> 7, k = idx & 127;
        float s = 0.f;
        #pragma unroll
        for (int j = 0; j < 7; j++) {
            int a = w - 3 + j, b = k - 3 + j;
            if (a >= 0 && a < 128 && b >= 0 && b < 128)
                s += G[a*GSTR + b];
        }
        Sout[idx] = s;
    }
}

// ---------------------------------------------------------------------------
// In-place prefix sums via float4 chains (4 adjacent k per thread):
// g_S over r (4096 float4-chains), g_tmp over h (2048 float4-chains).
// 24 blocks x 256 threads; MLP = 8 float4 loads per batch.
// ---------------------------------------------------------------------------
__global__ __launch_bounds__(256) void prefix_kernel()
{
    int t = blockIdx.x * 256 + threadIdx.x;
    float4 vals[8];
    if (t < 4096) {
        float4* p = (float4*)g_S;
        float4 s = make_float4(0.f, 0.f, 0.f, 0.f);
        for (int rb = 0; rb < 128; rb += 8) {
            #pragma unroll
            for (int i = 0; i < 8; i++) vals[i] = p[(rb + i) * 4096 + t];
            #pragma unroll
            for (int i = 0; i < 8; i++) {
                s.x += vals[i].x; s.y += vals[i].y;
                s.z += vals[i].z; s.w += vals[i].w;
                p[(rb + i) * 4096 + t] = s;
            }
        }
    } else {
        int u = t - 4096;               // u < 2048: c = u>>5, kq = u&31
        int base = (u >> 5) * 4096 + (u & 31);
        float4* p = (float4*)g_tmp;
        float4 s = make_float4(0.f, 0.f, 0.f, 0.f);
        for (int hb = 0; hb < 128; hb += 8) {
            #pragma unroll
            for (int i = 0; i < 8; i++) vals[i] = p[base + (hb + i) * 32];
            #pragma unroll
            for (int i = 0; i < 8; i++) {
                s.x += vals[i].x; s.y += vals[i].y;
                s.z += vals[i].z; s.w += vals[i].w;
                p[base + (hb + i) * 32] = s;
            }
        }
    }
}

// ---------------------------------------------------------------------------
// Per (h, w-half): A = PS[r1]-PS[r0-1]; softmax_k; Vs = Ptmp diff;
// out = attn @ Vs^T. 256 blocks x 256 threads, ~66KB smem -> 3 blocks/SM.
// ---------------------------------------------------------------------------
__global__ __launch_bounds__(256) void attn_out_kernel(float* __restrict__ out)
{
    extern __shared__ float sm[];
    float* A  = sm;                 // [64 local w][k], stride GSTR
    float* Vs = sm + 64*GSTR;       // [c=64][k=128] (float4-aligned: 8256%4==0)

    int h    = blockIdx.x >> 1;
    int half = blockIdx.x & 1;
    int tid = threadIdx.x;
    int lane = tid & 31, warp = tid >> 5;    // 8 warps

    int r0 = (h - 3 < 0) ? 0 : h - 3;
    int r1 = (h + 3 > 127) ? 127 : h + 3;
    const float4* P1 = (const float4*)(g_S + r1 * 16384 + half * 8192);
    const float4* P0 = (r0 > 0) ? (const float4*)(g_S + (r0 - 1) * 16384 + half * 8192) : nullptr;
    for (int i4 = tid; i4 < 2048; i4 += 256) {
        float4 s = P1[i4];
        if (P0) {
            float4 b = P0[i4];
            s.x -= b.x; s.y -= b.y; s.z -= b.z; s.w -= b.w;
        }
        int wl = i4 >> 5, k = (i4 & 31) * 4;
        float* dst = A + wl*GSTR + k;
        dst[0] = s.x; dst[1] = s.y; dst[2] = s.z; dst[3] = s.w;
    }

    int top = (h + 3 > 127) ? 127 : h + 3;
    int bot = h - 4;
    const float4* T4 = (const float4*)g_tmp;
    float4* Vs4 = (float4*)Vs;
    for (int i4 = tid; i4 < 2048; i4 += 256) {
        int c = i4 >> 5, kq = i4 & 31;
        float4 s = T4[c*4096 + top*32 + kq];
        if (bot >= 0) {
            float4 b = T4[c*4096 + bot*32 + kq];
            s.x -= b.x; s.y -= b.y; s.z -= b.z; s.w -= b.w;
        }
        Vs4[c*32 + kq] = s;
    }
    __syncthreads();

    // softmax over k: one warp per local-w row (8 warps cover 64 rows)
    for (int w = warp; w < 64; w += 8) {
        float v[4];
        #pragma unroll
        for (int m = 0; m < 4; m++) v[m] = A[w*GSTR + lane + 32*m];
        float mx = fmaxf(fmaxf(v[0], v[1]), fmaxf(v[2], v[3]));
        #pragma unroll
        for (int off = 16; off > 0; off >>= 1)
            mx = fmaxf(mx, __shfl_xor_sync(0xffffffffu, mx, off));
        float e[4], s = 0.f;
        #pragma unroll
        for (int m = 0; m < 4; m++) { e[m] = __expf(v[m] - mx); s += e[m]; }
        #pragma unroll
        for (int off = 16; off > 0; off >>= 1)
            s += __shfl_xor_sync(0xffffffffu, s, off);
        float inv = 1.f / s;
        #pragma unroll
        for (int m = 0; m < 4; m++) A[w*GSTR + lane + 32*m] = e[m] * inv;
    }
    __syncthreads();

    // out[c, h, half*64 + w] = sum_k A[w][k] * Vs[c][k]
    int c0 = warp * 8;
    float acc[8][2];
    #pragma unroll
    for (int i = 0; i < 8; i++)
        #pragma unroll
        for (int m = 0; m < 2; m++) acc[i][m] = 0.f;

    #pragma unroll 4
    for (int k = 0; k < 128; k++) {
        float a[2];
        #pragma unroll
        for (int m = 0; m < 2; m++) a[m] = A[(lane + 32*m)*GSTR + k];
        #pragma unroll
        for (int i = 0; i < 8; i++) {
            float vv = Vs[(c0 + i)*128 + k];
            #pragma unroll
            for (int m = 0; m < 2; m++) acc[i][m] += vv * a[m];
        }
    }
    int wbase = h*128 + half*64 + lane;
    #pragma unroll
    for (int i = 0; i < 8; i++)
        #pragma unroll
        for (int m = 0; m < 2; m++)
            out[(c0 + i)*NPIX + wbase + 32*m] = acc[i][m];
}

// ---------------------------------------------------------------------------
extern "C" void kernel_launch(void* const* d_in, const int* in_sizes, int n_in,
                              void* d_out, int out_size)
{
    const float* x  = (const float*)d_in[0];
    const float* Wq = (const float*)d_in[1];
    const float* bq = (const float*)d_in[2];
    const float* Wk = (const float*)d_in[3];
    const float* bk = (const float*)d_in[4];
    const float* Wv = (const float*)d_in[5];
    const float* bv = (const float*)d_in[6];
    float* out = (float*)d_out;

    const int smem1 = (4096 + 64 + 64*128) * 4;       //  49664 B
    const int smem2 = (8192 + 8192 + 128*GSTR) * 4;   // 131584 B
    const int smem4 = (64*GSTR + 64*128) * 4;         //  65792 B
    cudaFuncSetAttribute(qkv_kernel,      cudaFuncAttributeMaxDynamicSharedMemorySize, smem1);
    cudaFuncSetAttribute(rowgram_kernel,  cudaFuncAttributeMaxDynamicSharedMemorySize, smem2);
    cudaFuncSetAttribute(attn_out_kernel, cudaFuncAttributeMaxDynamicSharedMemorySize, smem4);

    dim3 qkv_grid(32, 3);
    qkv_kernel<<<qkv_grid, 512, smem1>>>(x, Wq, bq, Wk, bk, Wv, bv);
    rowgram_kernel<<<128, 512, smem2>>>();
    prefix_kernel<<<24, 256>>>();
    attn_out_kernel<<<256, 256, smem4>>>(out);
}

// round 8
// speedup vs baseline: 1.1316x; 1.1316x over previous
#include <cuda_runtime.h>

#define HH 128
#define WW 128
#define CC 64
#define NPIX (HH*WW)
#define GSTR 129

// scratch (allocation-free: __device__ globals)
__device__ float g_q[HH*CC*WW];   // [h][c][w]
__device__ float g_k[HH*CC*WW];   // [h][c][w]
__device__ float g_S[HH*WW*WW];   // [r][w][k]  (after prefix: PS over r)
__device__ float g_tmp[CC*HH*WW]; // [c][h][k]  hsum of v; after prefix: prefix over h

// ---------------------------------------------------------------------------
// Fused QKV: grid (32, 3); blockIdx.y selects q/k/v. For v, the horizontal
// 7-tap window sum is done in-block and written straight to g_tmp.
// Dynamic smem: Ws[4096] | bs[64] | vbuf[64*128]
// ---------------------------------------------------------------------------
__global__ __launch_bounds__(512) void qkv_kernel(const float* __restrict__ x,
                                                  const float* __restrict__ Wq,
                                                  const float* __restrict__ bq,
                                                  const float* __restrict__ Wk,
                                                  const float* __restrict__ bk,
                                                  const float* __restrict__ Wv,
                                                  const float* __restrict__ bv)
{
    extern __shared__ float dsm[];
    float* Ws   = dsm;          // 4096
    float* bs   = dsm + 4096;   // 64
    float* vbuf = dsm + 4160;   // 64*128 (dest==2 only)

    int dest = blockIdx.y;
    const float* Wm   = (dest == 0) ? Wq : (dest == 1) ? Wk : Wv;
    const float* bias = (dest == 0) ? bq : (dest == 1) ? bk : bv;
    int tid = threadIdx.x;
    for (int i = tid; i < 4096; i += 512) Ws[i] = Wm[i];
    if (tid < 64) bs[tid] = bias[tid];
    __syncthreads();

    int slot = tid & 127;            // w coordinate (full row per 128 threads)
    int quarter = tid >> 7;          // 16-channel group
    int nbase = blockIdx.x * 512 + slot;

    float acc[16][4];
    #pragma unroll
    for (int i = 0; i < 16; i++)
        #pragma unroll
        for (int p = 0; p < 4; p++) acc[i][p] = 0.f;

    #pragma unroll 2
    for (int c = 0; c < 64; c++) {
        float xv[4];
        #pragma unroll
        for (int p = 0; p < 4; p++) xv[p] = x[c * NPIX + nbase + 128 * p];
        #pragma unroll
        for (int i = 0; i < 16; i++) {
            float wv = Ws[(quarter*16 + i)*64 + c];
            #pragma unroll
            for (int p = 0; p < 4; p++) acc[i][p] += wv * xv[p];
        }
    }

    if (dest < 2) {
        float* out = (dest == 0) ? g_q : g_k;
        #pragma unroll
        for (int i = 0; i < 16; i++) {
            int ch = quarter*16 + i;
            float b = bs[ch];
            #pragma unroll
            for (int p = 0; p < 4; p++) {
                int n = nbase + 128 * p;
                int h = n >> 7, w = n & 127;
                out[h*(CC*WW) + ch*WW + w] = acc[i][p] + b;
            }
        }
    } else {
        // v path: stage each row in vbuf, 7-tap hsum, write g_tmp[c][h][w]
        for (int p = 0; p < 4; p++) {
            __syncthreads();
            #pragma unroll
            for (int i = 0; i < 16; i++) {
                int ch = quarter*16 + i;
                vbuf[ch*128 + slot] = acc[i][p] + bs[ch];
            }
            __syncthreads();
            int h = blockIdx.x*4 + p;
            int klo = (slot - 3 < 0) ? 0 : slot - 3;
            int khi = (slot + 3 > 127) ? 127 : slot + 3;
            #pragma unroll
            for (int i = 0; i < 16; i++) {
                int ch = quarter*16 + i;
                const float* vr = vbuf + ch*128;
                float s = 0.f;
                for (int kk = klo; kk <= khi; kk++) s += vr[kk];
                g_tmp[ch*NPIX + h*128 + slot] = s;
            }
        }
    }
}

// ---------------------------------------------------------------------------
// Per-row Gram G_r = Q_r^T K_r (64-deep), then diagonal 7-sum -> S_r.
// ---------------------------------------------------------------------------
__global__ __launch_bounds__(512) void rowgram_kernel()
{
    extern __shared__ float sm[];
    float* Qs = sm;            // 64 x 128
    float* Ks = sm + 8192;     // 64 x 128
    float* G  = sm + 16384;    // 128 x GSTR

    int r = blockIdx.x;
    int tid = threadIdx.x;
    const float4* qrow = (const float4*)(g_q + r * 8192);
    const float4* krow = (const float4*)(g_k + r * 8192);
    float4* Qs4 = (float4*)Qs;
    float4* Ks4 = (float4*)Ks;
    for (int i = tid; i < 2048; i += 512) { Qs4[i] = qrow[i]; Ks4[i] = krow[i]; }
    __syncthreads();

    int lane = tid & 31, warp = tid >> 5;    // 16 warps
    int b0 = warp * 8;
    float acc[4][8];
    #pragma unroll
    for (int m = 0; m < 4; m++)
        #pragma unroll
        for (int j = 0; j < 8; j++) acc[m][j] = 0.f;

    #pragma unroll 4
    for (int c = 0; c < 64; c++) {
        float qv[4];
        #pragma unroll
        for (int m = 0; m < 4; m++) qv[m] = Qs[c*128 + lane + 32*m];
        #pragma unroll
        for (int j = 0; j < 8; j++) {
            float kv = Ks[c*128 + b0 + j];
            #pragma unroll
            for (int m = 0; m < 4; m++) acc[m][j] += qv[m] * kv;
        }
    }
    #pragma unroll
    for (int m = 0; m < 4; m++)
        #pragma unroll
        for (int j = 0; j < 8; j++)
            G[(lane + 32*m)*GSTR + b0 + j] = acc[m][j];
    __syncthreads();

    // S_r[w,k] = sum_{j=0..6} G[w-3+j, k-3+j] (OOB terms are zero)
    float* Sout = g_S + r * 16384;
    for (int idx = tid; idx < 16384; idx += 512) {
        int w = idx >> 7, k = idx & 127;
        float s = 0.f;
        #pragma unroll
        for (int j = 0; j < 7; j++) {
            int a = w - 3 + j, b = k - 3 + j;
            if (a >= 0 && a < 128 && b >= 0 && b < 128)
                s += G[a*GSTR + b];
        }
        Sout[idx] = s;
    }
}

// ---------------------------------------------------------------------------
// In-place prefix sums: g_S over r (16384 scalar chains), g_tmp over h (8192).
// 96 blocks x 256 threads; MLP = 16 independent LDGs per batch.
// ---------------------------------------------------------------------------
__global__ __launch_bounds__(256) void prefix_kernel()
{
    int t = blockIdx.x * 256 + threadIdx.x;
    float vals[16];
    if (t < 16384) {
        float s = 0.f;
        float* p = g_S + t;
        #pragma unroll
        for (int rb = 0; rb < 128; rb += 16) {
            #pragma unroll
            for (int i = 0; i < 16; i++) vals[i] = p[(rb + i) * 16384];
            #pragma unroll
            for (int i = 0; i < 16; i++) { s += vals[i]; p[(rb + i) * 16384] = s; }
        }
    } else {
        int u = t - 16384;
        int c = u >> 7, k = u & 127;
        float s = 0.f;
        float* p = g_tmp + c * NPIX + k;
        #pragma unroll
        for (int hb = 0; hb < 128; hb += 16) {
            #pragma unroll
            for (int i = 0; i < 16; i++) vals[i] = p[(hb + i) * 128];
            #pragma unroll
            for (int i = 0; i < 16; i++) { s += vals[i]; p[(hb + i) * 128] = s; }
        }
    }
}

// ---------------------------------------------------------------------------
// Per (h, w-half): A = PS[r1]-PS[r0-1]; softmax_k; Vs = Ptmp diff;
// out = attn @ Vs^T. 256 blocks x 512 threads, ~66KB smem.
// ---------------------------------------------------------------------------
__global__ __launch_bounds__(512) void attn_out_kernel(float* __restrict__ out)
{
    extern __shared__ float sm[];
    float* A  = sm;                 // [64 local w][k], stride GSTR
    float* Vs = sm + 64*GSTR;       // [c=64][k=128]

    int h    = blockIdx.x >> 1;
    int half = blockIdx.x & 1;
    int tid = threadIdx.x;
    int lane = tid & 31, warp = tid >> 5;    // 16 warps

    int r0 = (h - 3 < 0) ? 0 : h - 3;
    int r1 = (h + 3 > 127) ? 127 : h + 3;
    const float4* P1 = (const float4*)(g_S + r1 * 16384 + half * 8192);
    const float4* P0 = (r0 > 0) ? (const float4*)(g_S + (r0 - 1) * 16384 + half * 8192) : nullptr;
    for (int i4 = tid; i4 < 2048; i4 += 512) {
        float4 s = P1[i4];
        if (P0) {
            float4 b = P0[i4];
            s.x -= b.x; s.y -= b.y; s.z -= b.z; s.w -= b.w;
        }
        int wl = i4 >> 5, k = (i4 & 31) * 4;
        float* dst = A + wl*GSTR + k;
        dst[0] = s.x; dst[1] = s.y; dst[2] = s.z; dst[3] = s.w;
    }

    int top = (h + 3 > 127) ? 127 : h + 3;
    int bot = h - 4;
    const float4* T4 = (const float4*)g_tmp;
    float4* Vs4 = (float4*)Vs;
    for (int i4 = tid; i4 < 2048; i4 += 512) {
        int c = i4 >> 5, kq = i4 & 31;
        float4 s = T4[c*4096 + top*32 + kq];
        if (bot >= 0) {
            float4 b = T4[c*4096 + bot*32 + kq];
            s.x -= b.x; s.y -= b.y; s.z -= b.z; s.w -= b.w;
        }
        Vs4[c*32 + kq] = s;
    }
    __syncthreads();

    // softmax over k: one warp per local-w row (16 warps cover 64 rows)
    for (int w = warp; w < 64; w += 16) {
        float v[4];
        #pragma unroll
        for (int m = 0; m < 4; m++) v[m] = A[w*GSTR + lane + 32*m];
        float mx = fmaxf(fmaxf(v[0], v[1]), fmaxf(v[2], v[3]));
        #pragma unroll
        for (int off = 16; off > 0; off >>= 1)
            mx = fmaxf(mx, __shfl_xor_sync(0xffffffffu, mx, off));
        float e[4], s = 0.f;
        #pragma unroll
        for (int m = 0; m < 4; m++) { e[m] = __expf(v[m] - mx); s += e[m]; }
        #pragma unroll
        for (int off = 16; off > 0; off >>= 1)
            s += __shfl_xor_sync(0xffffffffu, s, off);
        float inv = 1.f / s;
        #pragma unroll
        for (int m = 0; m < 4; m++) A[w*GSTR + lane + 32*m] = e[m] * inv;
    }
    __syncthreads();

    // out[c, h, half*64 + w] = sum_k A[w][k] * Vs[c][k]
    // 16 warps x 4 channels each; each thread 4c x 2w.
    int c0 = warp * 4;
    float acc[4][2];
    #pragma unroll
    for (int i = 0; i < 4; i++)
        #pragma unroll
        for (int m = 0; m < 2; m++) acc[i][m] = 0.f;

    #pragma unroll 4
    for (int k = 0; k < 128; k++) {
        float a[2];
        #pragma unroll
        for (int m = 0; m < 2; m++) a[m] = A[(lane + 32*m)*GSTR + k];
        #pragma unroll
        for (int i = 0; i < 4; i++) {
            float vv = Vs[(c0 + i)*128 + k];
            #pragma unroll
            for (int m = 0; m < 2; m++) acc[i][m] += vv * a[m];
        }
    }
    int wbase = h*128 + half*64 + lane;
    #pragma unroll
    for (int i = 0; i < 4; i++)
        #pragma unroll
        for (int m = 0; m < 2; m++)
            out[(c0 + i)*NPIX + wbase + 32*m] = acc[i][m];
}

// ---------------------------------------------------------------------------
extern "C" void kernel_launch(void* const* d_in, const int* in_sizes, int n_in,
                              void* d_out, int out_size)
{
    const float* x  = (const float*)d_in[0];
    const float* Wq = (const float*)d_in[1];
    const float* bq = (const float*)d_in[2];
    const float* Wk = (const float*)d_in[3];
    const float* bk = (const float*)d_in[4];
    const float* Wv = (const float*)d_in[5];
    const float* bv = (const float*)d_in[6];
    float* out = (float*)d_out;

    const int smem1 = (4096 + 64 + 64*128) * 4;       //  49664 B
    const int smem2 = (8192 + 8192 + 128*GSTR) * 4;   // 131584 B
    const int smem4 = (64*GSTR + 64*128) * 4;         //  65792 B
    cudaFuncSetAttribute(qkv_kernel,      cudaFuncAttributeMaxDynamicSharedMemorySize, smem1);
    cudaFuncSetAttribute(rowgram_kernel,  cudaFuncAttributeMaxDynamicSharedMemorySize, smem2);
    cudaFuncSetAttribute(attn_out_kernel, cudaFuncAttributeMaxDynamicSharedMemorySize, smem4);

    dim3 qkv_grid(32, 3);
    qkv_kernel<<<qkv_grid, 512, smem1>>>(x, Wq, bq, Wk, bk, Wv, bv);
    rowgram_kernel<<<128, 512, smem2>>>();
    prefix_kernel<<<96, 256>>>();
    attn_out_kernel<<<256, 512, smem4>>>(out);
}

// round 12
// speedup vs baseline: 1.1647x; 1.0292x over previous
#include <cuda_runtime.h>

#define HH 128
#define WW 128
#define CC 64
#define NPIX (HH*WW)
#define GSTR 129
#define ASTR 132   // A stride in attn_out: 132 % 32 == 4 -> conflict-free LDS.128

// scratch (allocation-free: __device__ globals)
__device__ float g_q[HH*CC*WW];   // [h][c][w]
__device__ float g_k[HH*CC*WW];   // [h][c][w]
__device__ float g_S[HH*WW*WW];   // [r][w][k]  (after prefix: PS over r)
__device__ float g_tmp[CC*HH*WW]; // [c][h][k]  hsum of v; after prefix: prefix over h

// ---------------------------------------------------------------------------
// Fused QKV: grid (32, 3); blockIdx.y selects q/k/v. For v, the horizontal
// 7-tap window sum is done in-block and written straight to g_tmp.
// ---------------------------------------------------------------------------
__global__ __launch_bounds__(512) void qkv_kernel(const float* __restrict__ x,
                                                  const float* __restrict__ Wq,
                                                  const float* __restrict__ bq,
                                                  const float* __restrict__ Wk,
                                                  const float* __restrict__ bk,
                                                  const float* __restrict__ Wv,
                                                  const float* __restrict__ bv)
{
    extern __shared__ float dsm[];
    float* Ws   = dsm;          // 4096
    float* bs   = dsm + 4096;   // 64
    float* vbuf = dsm + 4160;   // 64*128 (dest==2 only)

    int dest = blockIdx.y;
    const float* Wm   = (dest == 0) ? Wq : (dest == 1) ? Wk : Wv;
    const float* bias = (dest == 0) ? bq : (dest == 1) ? bk : bv;
    int tid = threadIdx.x;
    for (int i = tid; i < 4096; i += 512) Ws[i] = Wm[i];
    if (tid < 64) bs[tid] = bias[tid];
    __syncthreads();

    int slot = tid & 127;
    int quarter = tid >> 7;
    int nbase = blockIdx.x * 512 + slot;

    float acc[16][4];
    #pragma unroll
    for (int i = 0; i < 16; i++)
        #pragma unroll
        for (int p = 0; p < 4; p++) acc[i][p] = 0.f;

    #pragma unroll 2
    for (int c = 0; c < 64; c++) {
        float xv[4];
        #pragma unroll
        for (int p = 0; p < 4; p++) xv[p] = x[c * NPIX + nbase + 128 * p];
        #pragma unroll
        for (int i = 0; i < 16; i++) {
            float wv = Ws[(quarter*16 + i)*64 + c];
            #pragma unroll
            for (int p = 0; p < 4; p++) acc[i][p] += wv * xv[p];
        }
    }

    if (dest < 2) {
        float* out = (dest == 0) ? g_q : g_k;
        #pragma unroll
        for (int i = 0; i < 16; i++) {
            int ch = quarter*16 + i;
            float b = bs[ch];
            #pragma unroll
            for (int p = 0; p < 4; p++) {
                int n = nbase + 128 * p;
                int h = n >> 7, w = n & 127;
                out[h*(CC*WW) + ch*WW + w] = acc[i][p] + b;
            }
        }
    } else {
        for (int p = 0; p < 4; p++) {
            __syncthreads();
            #pragma unroll
            for (int i = 0; i < 16; i++) {
                int ch = quarter*16 + i;
                vbuf[ch*128 + slot] = acc[i][p] + bs[ch];
            }
            __syncthreads();
            int h = blockIdx.x*4 + p;
            int klo = (slot - 3 < 0) ? 0 : slot - 3;
            int khi = (slot + 3 > 127) ? 127 : slot + 3;
            #pragma unroll
            for (int i = 0; i < 16; i++) {
                int ch = quarter*16 + i;
                const float* vr = vbuf + ch*128;
                float s = 0.f;
                for (int kk = klo; kk <= khi; kk++) s += vr[kk];
                g_tmp[ch*NPIX + h*128 + slot] = s;
            }
        }
    }
}

// ---------------------------------------------------------------------------
// Per-row Gram G_r = Q_r^T K_r (64-deep), then diagonal 7-sum -> S_r.
// K operand loaded as float4 broadcasts (b0 = warp*8, 16B aligned).
// ---------------------------------------------------------------------------
__global__ __launch_bounds__(512) void rowgram_kernel()
{
    extern __shared__ float sm[];
    float* Qs = sm;            // 64 x 128
    float* Ks = sm + 8192;     // 64 x 128
    float* G  = sm + 16384;    // 128 x GSTR

    int r = blockIdx.x;
    int tid = threadIdx.x;
    const float4* qrow = (const float4*)(g_q + r * 8192);
    const float4* krow = (const float4*)(g_k + r * 8192);
    float4* Qs4 = (float4*)Qs;
    float4* Ks4 = (float4*)Ks;
    for (int i = tid; i < 2048; i += 512) { Qs4[i] = qrow[i]; Ks4[i] = krow[i]; }
    __syncthreads();

    int lane = tid & 31, warp = tid >> 5;    // 16 warps
    int b0 = warp * 8;
    float acc[4][8];
    #pragma unroll
    for (int m = 0; m < 4; m++)
        #pragma unroll
        for (int j = 0; j < 8; j++) acc[m][j] = 0.f;

    #pragma unroll 4
    for (int c = 0; c < 64; c++) {
        float qv[4];
        #pragma unroll
        for (int m = 0; m < 4; m++) qv[m] = Qs[c*128 + lane + 32*m];
        float4 k0 = *(const float4*)&Ks[c*128 + b0];
        float4 k1 = *(const float4*)&Ks[c*128 + b0 + 4];
        float kv[8] = {k0.x, k0.y, k0.z, k0.w, k1.x, k1.y, k1.z, k1.w};
        #pragma unroll
        for (int j = 0; j < 8; j++)
            #pragma unroll
            for (int m = 0; m < 4; m++) acc[m][j] += qv[m] * kv[j];
    }
    #pragma unroll
    for (int m = 0; m < 4; m++)
        #pragma unroll
        for (int j = 0; j < 8; j++)
            G[(lane + 32*m)*GSTR + b0 + j] = acc[m][j];
    __syncthreads();

    // S_r[w,k] = sum_{j=0..6} G[w-3+j, k-3+j] (OOB terms are zero)
    float* Sout = g_S + r * 16384;
    for (int idx = tid; idx < 16384; idx += 512) {
        int w = idx >> 7, k = idx & 127;
        float s = 0.f;
        #pragma unroll
        for (int j = 0; j < 7; j++) {
            int a = w - 3 + j, b = k - 3 + j;
            if (a >= 0 && a < 128 && b >= 0 && b < 128)
                s += G[a*GSTR + b];
        }
        Sout[idx] = s;
    }
}

// ---------------------------------------------------------------------------
// In-place prefix sums: g_S over r (16384 scalar chains), g_tmp over h (8192).
// 96 blocks x 256 threads; MLP = 16 independent LDGs per batch.
// ---------------------------------------------------------------------------
__global__ __launch_bounds__(256) void prefix_kernel()
{
    int t = blockIdx.x * 256 + threadIdx.x;
    float vals[16];
    if (t < 16384) {
        float s = 0.f;
        float* p = g_S + t;
        #pragma unroll
        for (int rb = 0; rb < 128; rb += 16) {
            #pragma unroll
            for (int i = 0; i < 16; i++) vals[i] = p[(rb + i) * 16384];
            #pragma unroll
            for (int i = 0; i < 16; i++) { s += vals[i]; p[(rb + i) * 16384] = s; }
        }
    } else {
        int u = t - 16384;
        int c = u >> 7, k = u & 127;
        float s = 0.f;
        float* p = g_tmp + c * NPIX + k;
        #pragma unroll
        for (int hb = 0; hb < 128; hb += 16) {
            #pragma unroll
            for (int i = 0; i < 16; i++) vals[i] = p[(hb + i) * 128];
            #pragma unroll
            for (int i = 0; i < 16; i++) { s += vals[i]; p[(hb + i) * 128] = s; }
        }
    }
}

// ---------------------------------------------------------------------------
// Per (h, w-half): A = PS[r1]-PS[r0-1]; softmax_k; Vs = Ptmp diff;
// out = attn @ Vs^T. 256 blocks x 512 threads.
// GEMM phase k-vectorized: LDS.128 for A (stride 132, conflict-free) and
// warp-uniform float4 broadcasts for Vs -> 6 LDS.128 per 32 FMA.
// ---------------------------------------------------------------------------
__global__ __launch_bounds__(512) void attn_out_kernel(float* __restrict__ out)
{
    extern __shared__ float sm[];
    float* A  = sm;                 // [64 local w][k], stride ASTR=132
    float* Vs = sm + 64*ASTR;       // [c=64][k=128] (offset 8448 -> 16B aligned)

    int h    = blockIdx.x >> 1;
    int half = blockIdx.x & 1;
    int tid = threadIdx.x;
    int lane = tid & 31, warp = tid >> 5;    // 16 warps

    int r0 = (h - 3 < 0) ? 0 : h - 3;
    int r1 = (h + 3 > 127) ? 127 : h + 3;
    const float4* P1 = (const float4*)(g_S + r1 * 16384 + half * 8192);
    const float4* P0 = (r0 > 0) ? (const float4*)(g_S + (r0 - 1) * 16384 + half * 8192) : nullptr;
    for (int i4 = tid; i4 < 2048; i4 += 512) {
        float4 s = P1[i4];
        if (P0) {
            float4 b = P0[i4];
            s.x -= b.x; s.y -= b.y; s.z -= b.z; s.w -= b.w;
        }
        int wl = i4 >> 5, k = (i4 & 31) * 4;
        *(float4*)(A + wl*ASTR + k) = s;
    }

    int top = (h + 3 > 127) ? 127 : h + 3;
    int bot = h - 4;
    const float4* T4 = (const float4*)g_tmp;
    float4* Vs4 = (float4*)Vs;
    for (int i4 = tid; i4 < 2048; i4 += 512) {
        int c = i4 >> 5, kq = i4 & 31;
        float4 s = T4[c*4096 + top*32 + kq];
        if (bot >= 0) {
            float4 b = T4[c*4096 + bot*32 + kq];
            s.x -= b.x; s.y -= b.y; s.z -= b.z; s.w -= b.w;
        }
        Vs4[c*32 + kq] = s;
    }
    __syncthreads();

    // softmax over k: one warp per local-w row (16 warps cover 64 rows)
    for (int w = warp; w < 64; w += 16) {
        float v[4];
        #pragma unroll
        for (int m = 0; m < 4; m++) v[m] = A[w*ASTR + lane + 32*m];
        float mx = fmaxf(fmaxf(v[0], v[1]), fmaxf(v[2], v[3]));
        #pragma unroll
        for (int off = 16; off > 0; off >>= 1)
            mx = fmaxf(mx, __shfl_xor_sync(0xffffffffu, mx, off));
        float e[4], s = 0.f;
        #pragma unroll
        for (int m = 0; m < 4; m++) { e[m] = __expf(v[m] - mx); s += e[m]; }
        #pragma unroll
        for (int off = 16; off > 0; off >>= 1)
            s += __shfl_xor_sync(0xffffffffu, s, off);
        float inv = 1.f / s;
        #pragma unroll
        for (int m = 0; m < 4; m++) A[w*ASTR + lane + 32*m] = e[m] * inv;
    }
    __syncthreads();

    // out[c, h, half*64 + w] = sum_k A[w][k] * Vs[c][k]
    // 16 warps x 4 channels; each thread 4c x 2w; k unrolled by 4 (float4).
    int c0 = warp * 4;
    float acc[4][2];
    #pragma unroll
    for (int i = 0; i < 4; i++)
        #pragma unroll
        for (int m = 0; m < 2; m++) acc[i][m] = 0.f;

    #pragma unroll 2
    for (int k = 0; k < 128; k += 4) {
        float4 a0 = *(const float4*)&A[lane*ASTR + k];
        float4 a1 = *(const float4*)&A[(lane + 32)*ASTR + k];
        #pragma unroll
        for (int i = 0; i < 4; i++) {
            float4 v = *(const float4*)&Vs[(c0 + i)*128 + k];
            acc[i][0] += v.x*a0.x + v.y*a0.y + v.z*a0.z + v.w*a0.w;
            acc[i][1] += v.x*a1.x + v.y*a1.y + v.z*a1.z + v.w*a1.w;
        }
    }
    int wbase = h*128 + half*64 + lane;
    #pragma unroll
    for (int i = 0; i < 4; i++)
        #pragma unroll
        for (int m = 0; m < 2; m++)
            out[(c0 + i)*NPIX + wbase + 32*m] = acc[i][m];
}

// ---------------------------------------------------------------------------
extern "C" void kernel_launch(void* const* d_in, const int* in_sizes, int n_in,
                              void* d_out, int out_size)
{
    const float* x  = (const float*)d_in[0];
    const float* Wq = (const float*)d_in[1];
    const float* bq = (const float*)d_in[2];
    const float* Wk = (const float*)d_in[3];
    const float* bk = (const float*)d_in[4];
    const float* Wv = (const float*)d_in[5];
    const float* bv = (const float*)d_in[6];
    float* out = (float*)d_out;

    const int smem1 = (4096 + 64 + 64*128) * 4;       //  49664 B
    const int smem2 = (8192 + 8192 + 128*GSTR) * 4;   // 131584 B
    const int smem4 = (64*ASTR + 64*128) * 4;         //  66560 B
    cudaFuncSetAttribute(qkv_kernel,      cudaFuncAttributeMaxDynamicSharedMemorySize, smem1);
    cudaFuncSetAttribute(rowgram_kernel,  cudaFuncAttributeMaxDynamicSharedMemorySize, smem2);
    cudaFuncSetAttribute(attn_out_kernel, cudaFuncAttributeMaxDynamicSharedMemorySize, smem4);

    dim3 qkv_grid(32, 3);
    qkv_kernel<<<qkv_grid, 512, smem1>>>(x, Wq, bq, Wk, bk, Wv, bv);
    rowgram_kernel<<<128, 512, smem2>>>();
    prefix_kernel<<<96, 256>>>();
    attn_out_kernel<<<256, 512, smem4>>>(out);
}

// round 13
// speedup vs baseline: 1.3187x; 1.1322x over previous
#include <cuda_runtime.h>

#define HH 128
#define WW 128
#define CC 64
#define NPIX (HH*WW)
#define GSTR 129
#define ASTR 132   // attn A stride: ≡4 mod 32 -> conflict-free LDS.128
#define QSTR 68    // rowgram Qt/Kt stride: ≡4 mod 32 -> conflict-free LDS.128

typedef unsigned long long u64;

__device__ __forceinline__ u64 fma2(u64 a, u64 b, u64 c) {
    u64 d;
    asm("fma.rn.f32x2 %0, %1, %2, %3;" : "=l"(d) : "l"(a), "l"(b), "l"(c));
    return d;
}
__device__ __forceinline__ u64 pack2(float x, float y) {
    u64 d;
    asm("mov.b64 %0, {%1, %2};" : "=l"(d) : "f"(x), "f"(y));
    return d;
}
__device__ __forceinline__ float2 unpack2(u64 v) {
    float2 r;
    asm("mov.b64 {%0, %1}, %2;" : "=f"(r.x), "=f"(r.y) : "l"(v));
    return r;
}

// scratch (allocation-free: __device__ globals)
__device__ float g_q[HH*WW*CC];   // [h][w][c]  (c contiguous!)
__device__ float g_k[HH*WW*CC];   // [h][w][c]
__device__ float g_S[HH*WW*WW];   // [r][w][k]  (after prefix: PS over r)
__device__ float g_tmp[CC*HH*WW]; // [c][h][k]  hsum of v; after prefix: prefix over h

// ---------------------------------------------------------------------------
// Fused QKV: grid (128, 3) = (h, dest); 512 threads; 1 image row per block.
// Thread = (slot=w, quarter=16ch). Reduction over c packed in f32x2 pairs.
// q,k stored [h][w][c]; v h-summed into g_tmp[c][h][w].
// Dynamic smem: Ws[4096] | bs[64] | vbuf[64*128]
// ---------------------------------------------------------------------------
__global__ __launch_bounds__(512) void qkv_kernel(const float* __restrict__ x,
                                                  const float* __restrict__ Wq,
                                                  const float* __restrict__ bq,
                                                  const float* __restrict__ Wk,
                                                  const float* __restrict__ bk,
                                                  const float* __restrict__ Wv,
                                                  const float* __restrict__ bv)
{
    extern __shared__ float dsm[];
    float* Ws   = dsm;          // [ch][c] 64x64
    float* bs   = dsm + 4096;
    float* vbuf = dsm + 4160;   // [ch][w] 64x128 (dest==2 only)

    int h = blockIdx.x;
    int dest = blockIdx.y;
    const float* Wm   = (dest == 0) ? Wq : (dest == 1) ? Wk : Wv;
    const float* bias = (dest == 0) ? bq : (dest == 1) ? bk : bv;
    int tid = threadIdx.x;
    for (int i = tid; i < 4096; i += 512) Ws[i] = Wm[i];
    if (tid < 64) bs[tid] = bias[tid];
    __syncthreads();

    int slot = tid & 127;            // w
    int quarter = tid >> 7;          // 16-channel group
    int ch0 = quarter * 16;
    int n = h * 128 + slot;

    u64 acc[16];
    #pragma unroll
    for (int i = 0; i < 16; i++) acc[i] = 0ull;

    #pragma unroll 4
    for (int c = 0; c < 64; c += 2) {
        float xa = x[c * NPIX + n];
        float xb = x[(c + 1) * NPIX + n];
        u64 xp = pack2(xa, xb);
        #pragma unroll
        for (int i = 0; i < 16; i++) {
            u64 wp = *(const u64*)&Ws[(ch0 + i) * 64 + c];
            acc[i] = fma2(xp, wp, acc[i]);
        }
    }

    if (dest < 2) {
        float* out = (dest == 0) ? g_q : g_k;
        float vals[16];
        #pragma unroll
        for (int i = 0; i < 16; i++) {
            float2 u = unpack2(acc[i]);
            vals[i] = u.x + u.y + bs[ch0 + i];
        }
        float* dst = out + h * (WW*CC) + slot * CC + ch0;
        #pragma unroll
        for (int i = 0; i < 4; i++)
            *(float4*)(dst + i*4) = make_float4(vals[i*4], vals[i*4+1],
                                                vals[i*4+2], vals[i*4+3]);
    } else {
        #pragma unroll
        for (int i = 0; i < 16; i++) {
            float2 u = unpack2(acc[i]);
            vbuf[(ch0 + i) * 128 + slot] = u.x + u.y + bs[ch0 + i];
        }
        __syncthreads();
        int klo = (slot - 3 < 0) ? 0 : slot - 3;
        int khi = (slot + 3 > 127) ? 127 : slot + 3;
        #pragma unroll
        for (int i = 0; i < 16; i++) {
            const float* vr = vbuf + (ch0 + i) * 128;
            float s = 0.f;
            for (int kk = klo; kk <= khi; kk++) s += vr[kk];
            g_tmp[(ch0 + i) * NPIX + h * 128 + slot] = s;
        }
    }
}

// ---------------------------------------------------------------------------
// Per-row Gram G_r = Q_r K_r^T over c (c-contiguous, f32x2-packed),
// then diagonal 7-sum -> S_r. 128 blocks x 512 threads.
// smem: Qt[128][QSTR] | Kt[128][QSTR] | G[128][GSTR]
// ---------------------------------------------------------------------------
__global__ __launch_bounds__(512) void rowgram_kernel()
{
    extern __shared__ float sm[];
    float* Qt = sm;                    // [w][c] stride QSTR
    float* Kt = sm + 128*QSTR;         // [w][c] stride QSTR
    float* G  = sm + 2*128*QSTR;       // [a][b] stride GSTR

    int r = blockIdx.x;
    int tid = threadIdx.x;
    const float4* qrow = (const float4*)(g_q + r * 8192);  // [w][c] c-contig
    const float4* krow = (const float4*)(g_k + r * 8192);
    for (int i = tid; i < 2048; i += 512) {
        int w = i >> 4, c4 = (i & 15) * 4;
        *(float4*)&Qt[w*QSTR + c4] = qrow[i];
        *(float4*)&Kt[w*QSTR + c4] = krow[i];
    }
    __syncthreads();

    int lane = tid & 31, warp = tid >> 5;    // 16 warps
    int b0 = warp * 8;
    u64 acc[4][8];
    #pragma unroll
    for (int m = 0; m < 4; m++)
        #pragma unroll
        for (int j = 0; j < 8; j++) acc[m][j] = 0ull;

    #pragma unroll 2
    for (int cc = 0; cc < 64; cc += 4) {
        ulonglong2 q4[4];
        #pragma unroll
        for (int m = 0; m < 4; m++)
            q4[m] = *(const ulonglong2*)&Qt[(lane + 32*m)*QSTR + cc];
        #pragma unroll
        for (int j = 0; j < 8; j++) {
            ulonglong2 k4 = *(const ulonglong2*)&Kt[(b0 + j)*QSTR + cc];
            #pragma unroll
            for (int m = 0; m < 4; m++) {
                acc[m][j] = fma2(q4[m].x, k4.x, acc[m][j]);
                acc[m][j] = fma2(q4[m].y, k4.y, acc[m][j]);
            }
        }
    }
    #pragma unroll
    for (int m = 0; m < 4; m++)
        #pragma unroll
        for (int j = 0; j < 8; j++) {
            float2 u = unpack2(acc[m][j]);
            G[(lane + 32*m)*GSTR + b0 + j] = u.x + u.y;
        }
    __syncthreads();

    // S_r[w,k] = sum_{j=0..6} G[w-3+j, k-3+j] (OOB terms are zero)
    float* Sout = g_S + r * 16384;
    for (int idx = tid; idx < 16384; idx += 512) {
        int w = idx >> 7, k = idx & 127;
        float s = 0.f;
        #pragma unroll
        for (int j = 0; j < 7; j++) {
            int a = w - 3 + j, b = k - 3 + j;
            if (a >= 0 && a < 128 && b >= 0 && b < 128)
                s += G[a*GSTR + b];
        }
        Sout[idx] = s;
    }
}

// ---------------------------------------------------------------------------
// In-place prefix sums: g_S over r (16384 scalar chains), g_tmp over h (8192).
// 96 blocks x 256 threads; MLP = 16 independent LDGs per batch.
// ---------------------------------------------------------------------------
__global__ __launch_bounds__(256) void prefix_kernel()
{
    int t = blockIdx.x * 256 + threadIdx.x;
    float vals[16];
    if (t < 16384) {
        float s = 0.f;
        float* p = g_S + t;
        #pragma unroll
        for (int rb = 0; rb < 128; rb += 16) {
            #pragma unroll
            for (int i = 0; i < 16; i++) vals[i] = p[(rb + i) * 16384];
            #pragma unroll
            for (int i = 0; i < 16; i++) { s += vals[i]; p[(rb + i) * 16384] = s; }
        }
    } else {
        int u = t - 16384;
        int c = u >> 7, k = u & 127;
        float s = 0.f;
        float* p = g_tmp + c * NPIX + k;
        #pragma unroll
        for (int hb = 0; hb < 128; hb += 16) {
            #pragma unroll
            for (int i = 0; i < 16; i++) vals[i] = p[(hb + i) * 128];
            #pragma unroll
            for (int i = 0; i < 16; i++) { s += vals[i]; p[(hb + i) * 128] = s; }
        }
    }
}

// ---------------------------------------------------------------------------
// Per (h, w-half): A = PS[r1]-PS[r0-1]; softmax_k; Vs = Ptmp diff;
// out = attn @ Vs^T with the k-reduction packed into f32x2 pairs.
// 256 blocks x 512 threads.
// ---------------------------------------------------------------------------
__global__ __launch_bounds__(512) void attn_out_kernel(float* __restrict__ out)
{
    extern __shared__ float sm[];
    float* A  = sm;                 // [64 local w][k], stride ASTR
    float* Vs = sm + 64*ASTR;       // [c=64][k=128]

    int h    = blockIdx.x >> 1;
    int half = blockIdx.x & 1;
    int tid = threadIdx.x;
    int lane = tid & 31, warp = tid >> 5;    // 16 warps

    int r0 = (h - 3 < 0) ? 0 : h - 3;
    int r1 = (h + 3 > 127) ? 127 : h + 3;
    const float4* P1 = (const float4*)(g_S + r1 * 16384 + half * 8192);
    const float4* P0 = (r0 > 0) ? (const float4*)(g_S + (r0 - 1) * 16384 + half * 8192) : nullptr;
    for (int i4 = tid; i4 < 2048; i4 += 512) {
        float4 s = P1[i4];
        if (P0) {
            float4 b = P0[i4];
            s.x -= b.x; s.y -= b.y; s.z -= b.z; s.w -= b.w;
        }
        int wl = i4 >> 5, k = (i4 & 31) * 4;
        *(float4*)(A + wl*ASTR + k) = s;
    }

    int top = (h + 3 > 127) ? 127 : h + 3;
    int bot = h - 4;
    const float4* T4 = (const float4*)g_tmp;
    float4* Vs4 = (float4*)Vs;
    for (int i4 = tid; i4 < 2048; i4 += 512) {
        int c = i4 >> 5, kq = i4 & 31;
        float4 s = T4[c*4096 + top*32 + kq];
        if (bot >= 0) {
            float4 b = T4[c*4096 + bot*32 + kq];
            s.x -= b.x; s.y -= b.y; s.z -= b.z; s.w -= b.w;
        }
        Vs4[c*32 + kq] = s;
    }
    __syncthreads();

    // softmax over k: one warp per local-w row (16 warps cover 64 rows)
    for (int w = warp; w < 64; w += 16) {
        float v[4];
        #pragma unroll
        for (int m = 0; m < 4; m++) v[m] = A[w*ASTR + lane + 32*m];
        float mx = fmaxf(fmaxf(v[0], v[1]), fmaxf(v[2], v[3]));
        #pragma unroll
        for (int off = 16; off > 0; off >>= 1)
            mx = fmaxf(mx, __shfl_xor_sync(0xffffffffu, mx, off));
        float e[4], s = 0.f;
        #pragma unroll
        for (int m = 0; m < 4; m++) { e[m] = __expf(v[m] - mx); s += e[m]; }
        #pragma unroll
        for (int off = 16; off > 0; off >>= 1)
            s += __shfl_xor_sync(0xffffffffu, s, off);
        float inv = 1.f / s;
        #pragma unroll
        for (int m = 0; m < 4; m++) A[w*ASTR + lane + 32*m] = e[m] * inv;
    }
    __syncthreads();

    // out[c, h, half*64 + w] = sum_k A[w][k] * Vs[c][k]  (k packed in pairs)
    int c0 = warp * 4;
    u64 acc[4][2];
    #pragma unroll
    for (int i = 0; i < 4; i++)
        #pragma unroll
        for (int m = 0; m < 2; m++) acc[i][m] = 0ull;

    #pragma unroll 2
    for (int k = 0; k < 128; k += 4) {
        ulonglong2 a0 = *(const ulonglong2*)&A[lane*ASTR + k];
        ulonglong2 a1 = *(const ulonglong2*)&A[(lane + 32)*ASTR + k];
        #pragma unroll
        for (int i = 0; i < 4; i++) {
            ulonglong2 v = *(const ulonglong2*)&Vs[(c0 + i)*128 + k];
            acc[i][0] = fma2(v.x, a0.x, acc[i][0]);
            acc[i][0] = fma2(v.y, a0.y, acc[i][0]);
            acc[i][1] = fma2(v.x, a1.x, acc[i][1]);
            acc[i][1] = fma2(v.y, a1.y, acc[i][1]);
        }
    }
    int wbase = h*128 + half*64 + lane;
    #pragma unroll
    for (int i = 0; i < 4; i++)
        #pragma unroll
        for (int m = 0; m < 2; m++) {
            float2 u = unpack2(acc[i][m]);
            out[(c0 + i)*NPIX + wbase + 32*m] = u.x + u.y;
        }
}

// ---------------------------------------------------------------------------
extern "C" void kernel_launch(void* const* d_in, const int* in_sizes, int n_in,
                              void* d_out, int out_size)
{
    const float* x  = (const float*)d_in[0];
    const float* Wq = (const float*)d_in[1];
    const float* bq = (const float*)d_in[2];
    const float* Wk = (const float*)d_in[3];
    const float* bk = (const float*)d_in[4];
    const float* Wv = (const float*)d_in[5];
    const float* bv = (const float*)d_in[6];
    float* out = (float*)d_out;

    const int smem1 = (4096 + 64 + 64*128) * 4;          //  49664 B
    const int smem2 = (2*128*QSTR + 128*GSTR) * 4;       // 135680 B
    const int smem4 = (64*ASTR + 64*128) * 4;            //  66560 B
    cudaFuncSetAttribute(qkv_kernel,      cudaFuncAttributeMaxDynamicSharedMemorySize, smem1);
    cudaFuncSetAttribute(rowgram_kernel,  cudaFuncAttributeMaxDynamicSharedMemorySize, smem2);
    cudaFuncSetAttribute(attn_out_kernel, cudaFuncAttributeMaxDynamicSharedMemorySize, smem4);

    dim3 qkv_grid(128, 3);
    qkv_kernel<<<qkv_grid, 512, smem1>>>(x, Wq, bq, Wk, bk, Wv, bv);
    rowgram_kernel<<<128, 512, smem2>>>();
    prefix_kernel<<<96, 256>>>();
    attn_out_kernel<<<256, 512, smem4>>>(out);
}